// round 6
// baseline (speedup 1.0000x reference)
#include <cuda_runtime.h>
#include <cuda_fp16.h>

#define BB  8
#define TT  1000
#define NHH 8
#define DD  64

// -(1/sqrt(64)) * log2(e), divided by int8 scale 256
#define QSCALE      256.0f
#define SCALE_COMB  (-0.18033688011112042f / 256.0f)

// Scratch (no allocs allowed)
__device__ unsigned g_qpack[BB*NHH*TT*16];  // int8x4 packed q, [b,h,t,dg]
__device__ unsigned g_kpack[BB*NHH*TT*16];  // int8x4 packed k
__device__ unsigned g_vpack[BB*NHH*TT*32];  // half2 packed v, [b,h,t,wp]
__device__ float    g_ho   [BB*NHH*TT*DD];  // per-head attention outputs

__device__ __forceinline__ int sad4_(int acc, unsigned a, unsigned b) {
  int r;
  asm("vabsdiff4.s32.s32.s32.add %0, %1, %2, %3;"
      : "=r"(r) : "r"(a), "r"(b), "r"(acc));
  return r;
}

__device__ __forceinline__ int q8_(float v) {
  int q = __float2int_rn(v * QSCALE);
  return max(-127, min(127, q));
}
__device__ __forceinline__ unsigned pack4_(int a, int b, int c, int d) {
  return (unsigned)(a & 255) | ((unsigned)(b & 255) << 8) |
         ((unsigned)(c & 255) << 16) | ((unsigned)(d & 255) << 24);
}

// ---------------------------------------------------------------------------
// K0: pack k = x * wk[h] -> int8x4. One thread per (h, token) pair.
// ---------------------------------------------------------------------------
__global__ __launch_bounds__(256) void kpack_kernel(
    const float* __restrict__ x, const float* __restrict__ wk) {
  __shared__ float xs[32][68];
  __shared__ float wks[512];
  const int tid = threadIdx.x;
  const int tok0 = blockIdx.x * 32;

  for (int i = tid; i < 512; i += 256) wks[i] = wk[i];
  for (int i = tid; i < 32*16; i += 256) {
    int tl = i >> 4, k4 = (i & 15) << 2;
    float4 v = *(const float4*)&x[(tok0 + tl)*DD + k4];
    xs[tl][k4+0] = v.x; xs[tl][k4+1] = v.y;
    xs[tl][k4+2] = v.z; xs[tl][k4+3] = v.w;
  }
  __syncthreads();

  const int h = tid >> 5, tl = tid & 31;
  const int gt = tok0 + tl;
  const int b = gt / TT, t = gt - b*TT;
  unsigned orow[16];
  #pragma unroll
  for (int dg = 0; dg < 16; dg++) {
    int d = dg << 2;
    orow[dg] = pack4_(q8_(xs[tl][d+0] * wks[h*64 + d+0]),
                      q8_(xs[tl][d+1] * wks[h*64 + d+1]),
                      q8_(xs[tl][d+2] * wks[h*64 + d+2]),
                      q8_(xs[tl][d+3] * wks[h*64 + d+3]));
  }
  unsigned* dst = g_kpack + ((size_t)(b*NHH + h)*TT + t)*16;
  #pragma unroll
  for (int i = 0; i < 4; i++)
    *(uint4*)&dst[i*4] = make_uint4(orow[i*4], orow[i*4+1], orow[i*4+2], orow[i*4+3]);
}

// ---------------------------------------------------------------------------
// K1: fused Q/V projection GEMM. z=0: q -> int8x4 pack; z=1: v -> half2 pack.
// ---------------------------------------------------------------------------
__global__ __launch_bounds__(256) void qv_kernel(
    const float* __restrict__ x, const float* __restrict__ wq,
    const float* __restrict__ wv) {
  const float* w = blockIdx.z ? wv : wq;
  const int m0 = blockIdx.x * 64;
  const int n0 = blockIdx.y * 64;

  __shared__ float xs[64*68];
  __shared__ float ws[64*68];
  const int tid = threadIdx.x;

  for (int i = tid; i < 64*16; i += 256) {
    int m = i >> 4, k4 = (i & 15) << 2;
    float4 v4 = *(const float4*)&x[(m0 + m)*DD + k4];
    xs[(k4+0)*68 + m] = v4.x;
    xs[(k4+1)*68 + m] = v4.y;
    xs[(k4+2)*68 + m] = v4.z;
    xs[(k4+3)*68 + m] = v4.w;
  }
  for (int i = tid; i < 64*64; i += 256) {
    int n = i >> 6, k = i & 63;
    ws[k*68 + n] = w[(n0 + n)*65 + k];
  }
  __syncthreads();

  const int tm = (tid >> 4) * 4;
  const int tn = (tid & 15) * 4;
  float acc[4][4];
  #pragma unroll
  for (int i = 0; i < 4; i++)
    #pragma unroll
    for (int j = 0; j < 4; j++) acc[i][j] = 0.f;

  #pragma unroll 8
  for (int k = 0; k < 64; k++) {
    float4 a4 = *(const float4*)&xs[k*68 + tm];
    float4 b4 = *(const float4*)&ws[k*68 + tn];
    float av[4] = {a4.x, a4.y, a4.z, a4.w};
    float bv[4] = {b4.x, b4.y, b4.z, b4.w};
    #pragma unroll
    for (int i = 0; i < 4; i++)
      #pragma unroll
      for (int j = 0; j < 4; j++) acc[i][j] += av[i] * bv[j];
  }

  const int n = n0 + tn;
  const int h = n >> 6, d0 = n & 63;
  float b0 = w[(n+0)*65 + 64];
  float b1 = w[(n+1)*65 + 64];
  float b2 = w[(n+2)*65 + 64];
  float b3 = w[(n+3)*65 + 64];

  #pragma unroll
  for (int i = 0; i < 4; i++) {
    int m = m0 + tm + i;
    int b = m / TT, t = m - b*TT;
    float f0 = acc[i][0] + b0, f1 = acc[i][1] + b1;
    float f2 = acc[i][2] + b2, f3 = acc[i][3] + b3;
    size_t row = (size_t)(b*NHH + h)*TT + t;
    if (blockIdx.z == 0) {
      g_qpack[row*16 + (d0 >> 2)] = pack4_(q8_(f0), q8_(f1), q8_(f2), q8_(f3));
    } else {
      __half2 h01 = __floats2half2_rn(f0, f1);
      __half2 h23 = __floats2half2_rn(f2, f3);
      uint2 o;
      o.x = *(unsigned*)&h01;
      o.y = *(unsigned*)&h23;
      *(uint2*)&g_vpack[row*32 + (d0 >> 1)] = o;
    }
  }
}

// ---------------------------------------------------------------------------
// K2: L1-distance attention.
//   scores: int8 SAD (vabsdiff4.add) on the ALU pipe, 4 dims/instr
//   AV:     HFMA2, 32-s chunks drained to fp32
// softmax max == 0 exactly (scores <= 0, null logit = 0): p=exp(s),
// denom = 1 + sum p (shared atomics).
// ---------------------------------------------------------------------------
__global__ __launch_bounds__(128, 4) void attn_kernel() {
  __shared__ unsigned qpk[16*68];   // [dg][t]  int8x4, stride 68
  __shared__ unsigned kpk[16*68];   // [dg][s]  int8x4, stride 68
  __shared__ unsigned vsh[64*32];   // [s][wp]  half2 bits
  __shared__ unsigned ps2[64*68];   // [s][t]   half2 duplicated, stride 68
  __shared__ float    denom[64];

  const int b  = blockIdx.z;
  const int h  = blockIdx.y;
  const int t0 = blockIdx.x * 64;
  const int tid = threadIdx.x;
  const int tt  = (tid & 15) * 4;  // 4 query rows
  const int g8  = (tid >> 4) * 8;  // 8 sources (score) / 8 dims (AV)
  const int sp0 = g8 >> 1;         // 4 half2 dim-pairs

  if (tid < 64) denom[tid] = 0.f;

  const unsigned* qpg = g_qpack + (size_t)(b*NHH + h)*TT*16;
  const unsigned* kpg = g_kpack + (size_t)(b*NHH + h)*TT*16;
  const unsigned* vpg = g_vpack + (size_t)(b*NHH + h)*TT*32;

  // load q tile transposed [dg][t]
  for (int i = tid; i < 256; i += 128) {
    int t = i >> 2, dg4 = (i & 3) << 2;
    int trow = t0 + t; if (trow >= TT) trow = TT - 1;  // clamp; masked later
    uint4 v = *(const uint4*)&qpg[(size_t)trow*16 + dg4];
    qpk[(dg4+0)*68 + t] = v.x;
    qpk[(dg4+1)*68 + t] = v.y;
    qpk[(dg4+2)*68 + t] = v.z;
    qpk[(dg4+3)*68 + t] = v.w;
  }
  __syncthreads();

  float oacc[4][8];
  #pragma unroll
  for (int i = 0; i < 4; i++)
    #pragma unroll
    for (int j = 0; j < 8; j++) oacc[i][j] = 0.f;

  for (int s0 = 0; s0 < TT; s0 += 64) {
    // load k transposed [dg][s], v direct [s][wp]
    for (int i = tid; i < 256; i += 128) {
      int s = i >> 2, dg4 = (i & 3) << 2;
      int srow = s0 + s; if (srow >= TT) srow = TT - 1;  // clamp; e masked to 0
      uint4 v = *(const uint4*)&kpg[(size_t)srow*16 + dg4];
      kpk[(dg4+0)*68 + s] = v.x;
      kpk[(dg4+1)*68 + s] = v.y;
      kpk[(dg4+2)*68 + s] = v.z;
      kpk[(dg4+3)*68 + s] = v.w;
    }
    for (int i = tid; i < 512; i += 128) {
      int s = i >> 3, w8 = (i & 7) << 2;
      int srow = s0 + s; if (srow >= TT) srow = TT - 1;  // p=0 kills it
      *(uint4*)&vsh[s*32 + w8] = *(const uint4*)&vpg[(size_t)srow*32 + w8];
    }
    __syncthreads();

    // ---- scores via SAD ----
    int sacc[4][8];
    #pragma unroll
    for (int i = 0; i < 4; i++)
      #pragma unroll
      for (int j = 0; j < 8; j++) sacc[i][j] = 0;

    #pragma unroll 8
    for (int dg = 0; dg < 16; dg++) {
      uint4 q4 = *(const uint4*)&qpk[dg*68 + tt];
      uint4 ka = *(const uint4*)&kpk[dg*68 + g8];
      uint4 kb = *(const uint4*)&kpk[dg*68 + g8 + 4];
      unsigned qa[4] = {q4.x, q4.y, q4.z, q4.w};
      unsigned kk[8] = {ka.x, ka.y, ka.z, ka.w, kb.x, kb.y, kb.z, kb.w};
      #pragma unroll
      for (int i = 0; i < 4; i++)
        #pragma unroll
        for (int j = 0; j < 8; j++)
          sacc[i][j] = sad4_(sacc[i][j], qa[i], kk[j]);
    }

    // e = exp2(SCALE_COMB * sad), masked past T
    float ef[4][8];
    #pragma unroll
    for (int i = 0; i < 4; i++)
      #pragma unroll
      for (int j = 0; j < 8; j++) {
        float f = (float)sacc[i][j] * SCALE_COMB;
        float e;
        asm("ex2.approx.f32 %0, %1;" : "=f"(e) : "f"(f));
        if (s0 + g8 + j >= TT) e = 0.f;
        ef[i][j] = e;
      }

    // denom partials: one shared atomic per query
    #pragma unroll
    for (int i = 0; i < 4; i++) {
      float ds = ((ef[i][0] + ef[i][1]) + (ef[i][2] + ef[i][3]))
               + ((ef[i][4] + ef[i][5]) + (ef[i][6] + ef[i][7]));
      atomicAdd(&denom[tt + i], ds);
    }

    // store p duplicated as half2, transposed [s][t]
    #pragma unroll
    for (int j = 0; j < 8; j++) {
      __half2 pv[4];
      pv[0] = __floats2half2_rn(ef[0][j], ef[0][j]);
      pv[1] = __floats2half2_rn(ef[1][j], ef[1][j]);
      pv[2] = __floats2half2_rn(ef[2][j], ef[2][j]);
      pv[3] = __floats2half2_rn(ef[3][j], ef[3][j]);
      *(uint4*)&ps2[(g8+j)*68 + tt] = *(uint4*)pv;
    }
    __syncthreads();

    // ---- AV: HFMA2, 32-s chunks drained to fp32 ----
    const __half2* pp2 = (const __half2*)ps2 + tt;
    const __half2* vp2 = (const __half2*)vsh + sp0;
    #pragma unroll
    for (int half_ = 0; half_ < 2; half_++) {
      __half2 oa2[4][4];
      #pragma unroll
      for (int i = 0; i < 4; i++)
        #pragma unroll
        for (int jp = 0; jp < 4; jp++) oa2[i][jp] = __float2half2_rn(0.f);

      #pragma unroll 4
      for (int ss = 0; ss < 32; ss++) {
        int s = half_*32 + ss;
        __half2 pb[4];
        *(uint4*)pb = *(const uint4*)(pp2 + s*68);
        __half2 vv[4];
        *(uint4*)vv = *(const uint4*)(vp2 + s*32);
        #pragma unroll
        for (int i = 0; i < 4; i++)
          #pragma unroll
          for (int jp = 0; jp < 4; jp++)
            oa2[i][jp] = __hfma2(pb[i], vv[jp], oa2[i][jp]);
      }
      #pragma unroll
      for (int i = 0; i < 4; i++)
        #pragma unroll
        for (int jp = 0; jp < 4; jp++) {
          float2 f = __half22float2(oa2[i][jp]);
          oacc[i][2*jp+0] += f.x;
          oacc[i][2*jp+1] += f.y;
        }
    }
    __syncthreads();
  }

  // normalize by (1 + sum p) and store per-head output
  float* hop = g_ho + (size_t)(b*NHH + h)*TT*DD;
  #pragma unroll
  for (int i = 0; i < 4; i++) {
    int trow = t0 + tt + i;
    if (trow < TT) {
      float inv = 1.f / (1.f + denom[tt + i]);
      float4 o1, o2;
      o1.x = oacc[i][0]*inv; o1.y = oacc[i][1]*inv;
      o1.z = oacc[i][2]*inv; o1.w = oacc[i][3]*inv;
      o2.x = oacc[i][4]*inv; o2.y = oacc[i][5]*inv;
      o2.z = oacc[i][6]*inv; o2.w = oacc[i][7]*inv;
      *(float4*)&hop[trow*DD + g8]     = o1;
      *(float4*)&hop[trow*DD + g8 + 4] = o2;
    }
  }
}

// ---------------------------------------------------------------------------
// K3: sum over heads, ReLU, y = Wf . r + bias, out = x + y.
// ---------------------------------------------------------------------------
__global__ __launch_bounds__(256) void out_kernel(
    const float* __restrict__ x, const float* __restrict__ wf,
    float* __restrict__ out) {
  __shared__ float r[4][64];
  __shared__ float wfs[64*65];
  const int tl = threadIdx.x >> 6;
  const int w  = threadIdx.x & 63;
  const int token = blockIdx.x*4 + tl;
  const int b = token / TT, t = token - b*TT;

  for (int i = threadIdx.x; i < 64*65; i += 256) wfs[i] = wf[i];

  float s = 0.f;
  #pragma unroll
  for (int h = 0; h < NHH; h++)
    s += g_ho[((size_t)(b*NHH + h)*TT + t)*DD + w];
  r[tl][w] = fmaxf(s, 0.f);
  __syncthreads();

  float acc = wfs[w*65 + 64];
  #pragma unroll 8
  for (int k = 0; k < 64; k++)
    acc += wfs[w*65 + k] * r[tl][k];

  out[(size_t)token*DD + w] = x[(size_t)token*DD + w] + acc;
}

// ---------------------------------------------------------------------------
extern "C" void kernel_launch(void* const* d_in, const int* in_sizes, int n_in,
                              void* d_out, int out_size) {
  const float* x  = (const float*)d_in[0];  // [8,1000,64]
  const float* wq = (const float*)d_in[1];  // [512,65]
  const float* wv = (const float*)d_in[2];  // [512,65]
  const float* wk = (const float*)d_in[3];  // [8,64]
  const float* wf = (const float*)d_in[4];  // [64,65]
  float* out = (float*)d_out;               // [8,1000,64]

  (void)in_sizes; (void)n_in; (void)out_size;

  kpack_kernel<<<BB*TT/32, 256>>>(x, wk);
  qv_kernel<<<dim3(8000/64, 512/64, 2), 256>>>(x, wq, wv);
  attn_kernel<<<dim3(16, NHH, BB), 128>>>();
  out_kernel<<<8000/4, 256>>>(x, wf, out);
}

// round 8
// speedup vs baseline: 5.5184x; 5.5184x over previous
#include <cuda_runtime.h>
#include <cuda_fp16.h>
#include <cstdint>

#define BB  8
#define TT  1000
#define NHH 8
#define DD  64
#define SCALE_LOG2E (-0.18033688011112042f)

__device__ __half g_qh[BB*NHH*TT*DD];
__device__ __half g_kh[BB*NHH*TT*DD];
__device__ __half g_vh[BB*NHH*TT*DD];
__device__ float  g_ho[BB*NHH*TT*DD];

__device__ __forceinline__ __half2 habs2_(__half2 a) {
  unsigned u = (*(unsigned*)&a) & 0x7FFF7FFFu;
  return *(__half2*)&u;
}
__device__ __forceinline__ unsigned smem_u32(const void* p) {
  return (unsigned)__cvta_generic_to_shared(p);
}

// K0: k = x*wk -> fp16
__global__ __launch_bounds__(256) void kpack_kernel(
    const float* __restrict__ x, const float* __restrict__ wk) {
  __shared__ float xs[32][68];
  __shared__ float wks[512];
  const int tid = threadIdx.x, tok0 = blockIdx.x * 32;
  for (int i = tid; i < 512; i += 256) wks[i] = wk[i];
  for (int i = tid; i < 512; i += 256) {
    int tl = i >> 4, k4 = (i & 15) << 2;
    float4 v = *(const float4*)&x[(tok0 + tl)*DD + k4];
    xs[tl][k4] = v.x; xs[tl][k4+1] = v.y; xs[tl][k4+2] = v.z; xs[tl][k4+3] = v.w;
  }
  __syncthreads();
  const int h = tid >> 5, tl = tid & 31;
  const int gt = tok0 + tl, b = gt / TT, t = gt - b*TT;
  __half* dst = g_kh + ((size_t)(b*NHH + h)*TT + t)*DD;
  #pragma unroll
  for (int c = 0; c < 8; c++) {
    int d = c*8;
    __half2 h0 = __floats2half2_rn(xs[tl][d]*wks[h*64+d],     xs[tl][d+1]*wks[h*64+d+1]);
    __half2 h1 = __floats2half2_rn(xs[tl][d+2]*wks[h*64+d+2], xs[tl][d+3]*wks[h*64+d+3]);
    __half2 h2 = __floats2half2_rn(xs[tl][d+4]*wks[h*64+d+4], xs[tl][d+5]*wks[h*64+d+5]);
    __half2 h3 = __floats2half2_rn(xs[tl][d+6]*wks[h*64+d+6], xs[tl][d+7]*wks[h*64+d+7]);
    uint4 o; o.x=*(unsigned*)&h0; o.y=*(unsigned*)&h1; o.z=*(unsigned*)&h2; o.w=*(unsigned*)&h3;
    *(uint4*)(dst + d) = o;
  }
}

// K1: Q/V projection -> fp16 [b,h][t][d]; z selects q vs v
__global__ __launch_bounds__(256) void qv_kernel(
    const float* __restrict__ x, const float* __restrict__ wq,
    const float* __restrict__ wv) {
  const float* w = blockIdx.z ? wv : wq;
  __half* dstg   = blockIdx.z ? g_vh : g_qh;
  const int m0 = blockIdx.x * 64, n0 = blockIdx.y * 64;
  __shared__ float xs[64*68];
  __shared__ float ws[64*68];
  const int tid = threadIdx.x;
  for (int i = tid; i < 1024; i += 256) {
    int m = i >> 4, k4 = (i & 15) << 2;
    float4 v4 = *(const float4*)&x[(m0 + m)*DD + k4];
    xs[(k4)*68+m]=v4.x; xs[(k4+1)*68+m]=v4.y; xs[(k4+2)*68+m]=v4.z; xs[(k4+3)*68+m]=v4.w;
  }
  for (int i = tid; i < 4096; i += 256) {
    int n = i >> 6, k = i & 63;
    ws[k*68 + n] = w[(n0 + n)*65 + k];
  }
  __syncthreads();
  const int tm = (tid >> 4) * 4, tn = (tid & 15) * 4;
  float acc[4][4];
  #pragma unroll
  for (int i = 0; i < 4; i++)
    #pragma unroll
    for (int j = 0; j < 4; j++) acc[i][j] = 0.f;
  #pragma unroll 8
  for (int k = 0; k < 64; k++) {
    float4 a4 = *(const float4*)&xs[k*68 + tm];
    float4 b4 = *(const float4*)&ws[k*68 + tn];
    float av[4] = {a4.x,a4.y,a4.z,a4.w}, bv[4] = {b4.x,b4.y,b4.z,b4.w};
    #pragma unroll
    for (int i = 0; i < 4; i++)
      #pragma unroll
      for (int j = 0; j < 4; j++) acc[i][j] += av[i]*bv[j];
  }
  const int n = n0 + tn, h = n >> 6, d0 = n & 63;
  float b0=w[n*65+64], b1=w[(n+1)*65+64], b2=w[(n+2)*65+64], b3=w[(n+3)*65+64];
  #pragma unroll
  for (int i = 0; i < 4; i++) {
    int m = m0 + tm + i, b = m / TT, t = m - b*TT;
    __half2 h01 = __floats2half2_rn(acc[i][0]+b0, acc[i][1]+b1);
    __half2 h23 = __floats2half2_rn(acc[i][2]+b2, acc[i][3]+b3);
    uint2 o; o.x=*(unsigned*)&h01; o.y=*(unsigned*)&h23;
    *(uint2*)(dstg + ((size_t)(b*NHH+h)*TT + t)*DD + d0) = o;
  }
}

// K2: scores fp16x2 (fma pipe); P*V via mma.sync m16n8k16 (tensor pipe, f32 accum).
// CTA = (b,h,64q), 128 thr. Score thread: 4q (tt) x 8s (g8). AV warp: 16 rows.
#define SM_QSH2  0                   // half2 [64 d][72 t] dup        18432
#define SM_KSH   18432               // half2 [64 d][36 sp]            9216
#define SM_PSM   27648               // half  [64 s][88 t]            11264
#define SM_VSM   38912               // half  [64 s][88 w]            11264
#define SM_DEN   50176               // float [64]
#define ATTN_SMEM 50432

__global__ __launch_bounds__(128, 4) void attn_kernel() {
  extern __shared__ char sm[];
  __half2*  qsh2 = (__half2*)(sm + SM_QSH2);
  unsigned* ksh  = (unsigned*)(sm + SM_KSH);
  __half*   psm  = (__half*)(sm + SM_PSM);
  __half*   vsm  = (__half*)(sm + SM_VSM);
  float*    den  = (float*)(sm + SM_DEN);

  const int tid = threadIdx.x, wid = tid >> 5, lid = tid & 31;
  const int bh = blockIdx.z*NHH + blockIdx.y;
  const int t0 = blockIdx.x * 64;
  const int tt = (tid & 15) * 4, g8 = (tid >> 4) * 8, sp0 = g8 >> 1;

  if (tid < 64) den[tid] = 0.f;

  const __half* qhg = g_qh + (size_t)bh*TT*DD;
  const __half* khg = g_kh + (size_t)bh*TT*DD;
  const __half* vhg = g_vh + (size_t)bh*TT*DD;

  // q -> qsh2[d][t] duplicated half2
  for (int i = tid; i < 1024; i += 128) {
    int t = i >> 4, k4 = (i & 15) << 2;
    int tr = t0 + t; if (tr >= TT) tr = TT - 1;
    uint2 qa = *(const uint2*)(qhg + (size_t)tr*DD + k4);
    unsigned d0 = __byte_perm(qa.x, 0, 0x1010), d1 = __byte_perm(qa.x, 0, 0x3232);
    unsigned d2 = __byte_perm(qa.y, 0, 0x1010), d3 = __byte_perm(qa.y, 0, 0x3232);
    qsh2[(k4)*72+t]   = *(__half2*)&d0;
    qsh2[(k4+1)*72+t] = *(__half2*)&d1;
    qsh2[(k4+2)*72+t] = *(__half2*)&d2;
    qsh2[(k4+3)*72+t] = *(__half2*)&d3;
  }
  __syncthreads();

  // ldmatrix lane bases (halfs): A from psm [s=k][t=m], B from vsm [s=k][w=n]
  const int m0 = wid * 16;
  const unsigned psm_s = smem_u32(psm), vsm_s = smem_u32(vsm);
  const unsigned aoff = ((lid & 7) + ((lid >> 4) & 1)*8)*88 + m0 + ((lid >> 3) & 1)*8;
  const unsigned boff = ((lid & 7) + ((lid >> 3) & 1)*8)*88 + ((lid >> 4) & 1)*8;

  float oc[8][4];
  #pragma unroll
  for (int nt = 0; nt < 8; nt++)
    #pragma unroll
    for (int r = 0; r < 4; r++) oc[nt][r] = 0.f;

  for (int s0 = 0; s0 < TT; s0 += 64) {
    // loaders: k pairs -> ksh[d][sp]; v rows -> vsm[s][w]
    for (int j = tid; j < 512; j += 128) {
      int sp = j >> 4, c4 = (j & 15) << 2;
      int r0 = s0 + 2*sp, r1 = r0 + 1;
      if (r0 >= TT) r0 = TT - 1;
      if (r1 >= TT) r1 = TT - 1;
      uint2 a = *(const uint2*)(khg + (size_t)r0*DD + c4);
      uint2 c = *(const uint2*)(khg + (size_t)r1*DD + c4);
      ksh[(c4)*36+sp]   = __byte_perm(a.x, c.x, 0x5410);
      ksh[(c4+1)*36+sp] = __byte_perm(a.x, c.x, 0x7632);
      ksh[(c4+2)*36+sp] = __byte_perm(a.y, c.y, 0x5410);
      ksh[(c4+3)*36+sp] = __byte_perm(a.y, c.y, 0x7632);
    }
    for (int j = tid; j < 512; j += 128) {
      int s = j >> 3, c = j & 7;
      int sr = s0 + s; if (sr >= TT) sr = TT - 1;   // P=0 kills garbage
      *(uint4*)(vsm + s*88 + c*8) = *(const uint4*)(vhg + (size_t)sr*DD + c*8);
    }
    __syncthreads();

    // scores (R4 code): sc2[i][jp], chunked fp32 drain
    float sacc[4][8];
    #pragma unroll
    for (int i = 0; i < 4; i++)
      #pragma unroll
      for (int j = 0; j < 8; j++) sacc[i][j] = 0.f;
    const __half2* qp2 = qsh2 + tt;
    const __half2* kp2 = (const __half2*)ksh + sp0;
    #pragma unroll
    for (int dc = 0; dc < 4; dc++) {
      __half2 sc2[4][4];
      #pragma unroll
      for (int i = 0; i < 4; i++)
        #pragma unroll
        for (int jp = 0; jp < 4; jp++) sc2[i][jp] = __float2half2_rn(0.f);
      #pragma unroll 4
      for (int dd = 0; dd < 16; dd++) {
        int d = dc*16 + dd;
        __half2 qq[4]; *(uint4*)qq = *(const uint4*)(qp2 + d*72);
        __half2 kk[4]; *(uint4*)kk = *(const uint4*)(kp2 + d*36);
        #pragma unroll
        for (int i = 0; i < 4; i++)
          #pragma unroll
          for (int jp = 0; jp < 4; jp++)
            sc2[i][jp] = __hadd2(sc2[i][jp], habs2_(__hsub2(qq[i], kk[jp])));
      }
      #pragma unroll
      for (int i = 0; i < 4; i++)
        #pragma unroll
        for (int jp = 0; jp < 4; jp++) {
          float2 f = __half22float2(sc2[i][jp]);
          sacc[i][2*jp]   += f.x;
          sacc[i][2*jp+1] += f.y;
        }
    }
    // e = exp2(scale*sum), mask past T
    #pragma unroll
    for (int i = 0; i < 4; i++)
      #pragma unroll
      for (int j = 0; j < 8; j++) {
        float e;
        asm("ex2.approx.f32 %0, %1;" : "=f"(e) : "f"(sacc[i][j] * SCALE_LOG2E));
        if (s0 + g8 + j >= TT) e = 0.f;
        sacc[i][j] = e;
      }
    // denom partials
    #pragma unroll
    for (int i = 0; i < 4; i++) {
      float ds = ((sacc[i][0]+sacc[i][1]) + (sacc[i][2]+sacc[i][3]))
               + ((sacc[i][4]+sacc[i][5]) + (sacc[i][6]+sacc[i][7]));
      atomicAdd(&den[tt + i], ds);
    }
    // store P[s][t] half (rows = sources)
    #pragma unroll
    for (int j = 0; j < 8; j++) {
      __half2 p01 = __floats2half2_rn(sacc[0][j], sacc[1][j]);
      __half2 p23 = __floats2half2_rn(sacc[2][j], sacc[3][j]);
      uint2 o; o.x = *(unsigned*)&p01; o.y = *(unsigned*)&p23;
      *(uint2*)(psm + (g8+j)*88 + tt) = o;
    }
    __syncthreads();

    // AV: A = P (16 rows m0), B = V; f32 accum in oc
    unsigned a[4][4];
    #pragma unroll
    for (int kk = 0; kk < 4; kk++) {
      unsigned ad = psm_s + (aoff + kk*16*88)*2;
      asm volatile("ldmatrix.sync.aligned.m8n8.x4.trans.shared.b16 {%0,%1,%2,%3}, [%4];"
        : "=r"(a[kk][0]),"=r"(a[kk][1]),"=r"(a[kk][2]),"=r"(a[kk][3]) : "r"(ad));
    }
    #pragma unroll
    for (int np = 0; np < 4; np++) {
      #pragma unroll
      for (int kk = 0; kk < 4; kk++) {
        unsigned b0,b1,b2,b3;
        unsigned bd = vsm_s + (boff + kk*16*88 + np*16)*2;
        asm volatile("ldmatrix.sync.aligned.m8n8.x4.trans.shared.b16 {%0,%1,%2,%3}, [%4];"
          : "=r"(b0),"=r"(b1),"=r"(b2),"=r"(b3) : "r"(bd));
        asm volatile(
          "mma.sync.aligned.m16n8k16.row.col.f32.f16.f16.f32 "
          "{%0,%1,%2,%3}, {%4,%5,%6,%7}, {%8,%9}, {%0,%1,%2,%3};"
          : "+f"(oc[2*np][0]),"+f"(oc[2*np][1]),"+f"(oc[2*np][2]),"+f"(oc[2*np][3])
          : "r"(a[kk][0]),"r"(a[kk][1]),"r"(a[kk][2]),"r"(a[kk][3]), "r"(b0),"r"(b1));
        asm volatile(
          "mma.sync.aligned.m16n8k16.row.col.f32.f16.f16.f32 "
          "{%0,%1,%2,%3}, {%4,%5,%6,%7}, {%8,%9}, {%0,%1,%2,%3};"
          : "+f"(oc[2*np+1][0]),"+f"(oc[2*np+1][1]),"+f"(oc[2*np+1][2]),"+f"(oc[2*np+1][3])
          : "r"(a[kk][0]),"r"(a[kk][1]),"r"(a[kk][2]),"r"(a[kk][3]), "r"(b2),"r"(b3));
      }
    }
    __syncthreads();
  }

  // epilogue: fragment rows m0+(lid>>2), m0+8+(lid>>2); cols 8nt+2(lid&3)
  const int rlo = m0 + (lid >> 2), rhi = rlo + 8;
  const int tlo = t0 + rlo, thi = t0 + rhi;
  const float invlo = 1.f / (1.f + den[rlo]);
  const float invhi = 1.f / (1.f + den[rhi]);
  float* hop = g_ho + (size_t)bh*TT*DD;
  #pragma unroll
  for (int nt = 0; nt < 8; nt++) {
    int c = nt*8 + 2*(lid & 3);
    if (tlo < TT) {
      float2 o; o.x = oc[nt][0]*invlo; o.y = oc[nt][1]*invlo;
      *(float2*)(hop + (size_t)tlo*DD + c) = o;
    }
    if (thi < TT) {
      float2 o; o.x = oc[nt][2]*invhi; o.y = oc[nt][3]*invhi;
      *(float2*)(hop + (size_t)thi*DD + c) = o;
    }
  }
}

// K3: head-sum + ReLU + Wf + residual
__global__ __launch_bounds__(256) void out_kernel(
    const float* __restrict__ x, const float* __restrict__ wf,
    float* __restrict__ out) {
  __shared__ float r[4][64];
  __shared__ float wfs[64*65];
  const int tl = threadIdx.x >> 6, w = threadIdx.x & 63;
  const int token = blockIdx.x*4 + tl, b = token / TT, t = token - b*TT;
  for (int i = threadIdx.x; i < 4160; i += 256) wfs[i] = wf[i];
  float s = 0.f;
  #pragma unroll
  for (int h = 0; h < NHH; h++)
    s += g_ho[((size_t)(b*NHH + h)*TT + t)*DD + w];
  r[tl][w] = fmaxf(s, 0.f);
  __syncthreads();
  float acc = wfs[w*65 + 64];
  #pragma unroll 8
  for (int k = 0; k < 64; k++) acc += wfs[w*65 + k] * r[tl][k];
  out[(size_t)token*DD + w] = x[(size_t)token*DD + w] + acc;
}

extern "C" void kernel_launch(void* const* d_in, const int* in_sizes, int n_in,
                              void* d_out, int out_size) {
  const float* x  = (const float*)d_in[0];
  const float* wq = (const float*)d_in[1];
  const float* wv = (const float*)d_in[2];
  const float* wk = (const float*)d_in[3];
  const float* wf = (const float*)d_in[4];
  float* out = (float*)d_out;
  (void)in_sizes; (void)n_in; (void)out_size;

  cudaFuncSetAttribute(attn_kernel, cudaFuncAttributeMaxDynamicSharedMemorySize,
                       ATTN_SMEM);
  kpack_kernel<<<BB*TT/32, 256>>>(x, wk);
  qv_kernel<<<dim3(8000/64, 512/64, 2), 256>>>(x, wq, wv);
  attn_kernel<<<dim3(16, NHH, BB), 128, ATTN_SMEM>>>();
  out_kernel<<<8000/4, 256>>>(x, wf, out);
}

// round 9
// speedup vs baseline: 5.5575x; 1.0071x over previous
#include <cuda_runtime.h>
#include <cuda_fp16.h>
#include <cstdint>

#define BB  8
#define TT  1000
#define NHH 8
#define DD  64
#define SCALE_LOG2E (-0.18033688011112042f)

__device__ __half g_qh[BB*NHH*TT*DD];
__device__ __half g_kh[BB*NHH*TT*DD];
__device__ __half g_vh[BB*NHH*TT*DD];
__device__ __half g_hoh[BB*NHH*TT*DD];

__device__ __forceinline__ __half2 habs2_(__half2 a) {
  unsigned u = (*(unsigned*)&a) & 0x7FFF7FFFu;
  return *(__half2*)&u;
}
__device__ __forceinline__ unsigned smem_u32(const void* p) {
  return (unsigned)__cvta_generic_to_shared(p);
}

// K0: k = x*wk -> fp16
__global__ __launch_bounds__(256) void kpack_kernel(
    const float* __restrict__ x, const float* __restrict__ wk) {
  __shared__ float xs[32][68];
  __shared__ float wks[512];
  const int tid = threadIdx.x, tok0 = blockIdx.x * 32;
  for (int i = tid; i < 512; i += 256) wks[i] = wk[i];
  for (int i = tid; i < 512; i += 256) {
    int tl = i >> 4, k4 = (i & 15) << 2;
    float4 v = *(const float4*)&x[(tok0 + tl)*DD + k4];
    xs[tl][k4] = v.x; xs[tl][k4+1] = v.y; xs[tl][k4+2] = v.z; xs[tl][k4+3] = v.w;
  }
  __syncthreads();
  const int h = tid >> 5, tl = tid & 31;
  const int gt = tok0 + tl, b = gt / TT, t = gt - b*TT;
  __half* dst = g_kh + ((size_t)(b*NHH + h)*TT + t)*DD;
  #pragma unroll
  for (int c = 0; c < 8; c++) {
    int d = c*8;
    __half2 h0 = __floats2half2_rn(xs[tl][d]*wks[h*64+d],     xs[tl][d+1]*wks[h*64+d+1]);
    __half2 h1 = __floats2half2_rn(xs[tl][d+2]*wks[h*64+d+2], xs[tl][d+3]*wks[h*64+d+3]);
    __half2 h2 = __floats2half2_rn(xs[tl][d+4]*wks[h*64+d+4], xs[tl][d+5]*wks[h*64+d+5]);
    __half2 h3 = __floats2half2_rn(xs[tl][d+6]*wks[h*64+d+6], xs[tl][d+7]*wks[h*64+d+7]);
    uint4 o; o.x=*(unsigned*)&h0; o.y=*(unsigned*)&h1; o.z=*(unsigned*)&h2; o.w=*(unsigned*)&h3;
    *(uint4*)(dst + d) = o;
  }
}

// K1: Q/V projection -> fp16 [b,h][t][d]
__global__ __launch_bounds__(256) void qv_kernel(
    const float* __restrict__ x, const float* __restrict__ wq,
    const float* __restrict__ wv) {
  const float* w = blockIdx.z ? wv : wq;
  __half* dstg   = blockIdx.z ? g_vh : g_qh;
  const int m0 = blockIdx.x * 64, n0 = blockIdx.y * 64;
  __shared__ float xs[64*68];
  __shared__ float ws[64*68];
  const int tid = threadIdx.x;
  for (int i = tid; i < 1024; i += 256) {
    int m = i >> 4, k4 = (i & 15) << 2;
    float4 v4 = *(const float4*)&x[(m0 + m)*DD + k4];
    xs[(k4)*68+m]=v4.x; xs[(k4+1)*68+m]=v4.y; xs[(k4+2)*68+m]=v4.z; xs[(k4+3)*68+m]=v4.w;
  }
  for (int i = tid; i < 4096; i += 256) {
    int n = i >> 6, k = i & 63;
    ws[k*68 + n] = w[(n0 + n)*65 + k];
  }
  __syncthreads();
  const int tm = (tid >> 4) * 4, tn = (tid & 15) * 4;
  float acc[4][4];
  #pragma unroll
  for (int i = 0; i < 4; i++)
    #pragma unroll
    for (int j = 0; j < 4; j++) acc[i][j] = 0.f;
  #pragma unroll 8
  for (int k = 0; k < 64; k++) {
    float4 a4 = *(const float4*)&xs[k*68 + tm];
    float4 b4 = *(const float4*)&ws[k*68 + tn];
    float av[4] = {a4.x,a4.y,a4.z,a4.w}, bv[4] = {b4.x,b4.y,b4.z,b4.w};
    #pragma unroll
    for (int i = 0; i < 4; i++)
      #pragma unroll
      for (int j = 0; j < 4; j++) acc[i][j] += av[i]*bv[j];
  }
  const int n = n0 + tn, h = n >> 6, d0 = n & 63;
  float b0=w[n*65+64], b1=w[(n+1)*65+64], b2=w[(n+2)*65+64], b3=w[(n+3)*65+64];
  #pragma unroll
  for (int i = 0; i < 4; i++) {
    int m = m0 + tm + i, b = m / TT, t = m - b*TT;
    __half2 h01 = __floats2half2_rn(acc[i][0]+b0, acc[i][1]+b1);
    __half2 h23 = __floats2half2_rn(acc[i][2]+b2, acc[i][3]+b3);
    uint2 o; o.x=*(unsigned*)&h01; o.y=*(unsigned*)&h23;
    *(uint2*)(dstg + ((size_t)(b*NHH+h)*TT + t)*DD + d0) = o;
  }
}

// K2 smem (bytes): qsh half[64][72]=9216 @0; ksh 2x9216 @9216;
// vsm 2x9216 @27648; psm 9216 @46080; den 256 @55296. Total 55552 -> occ 4.
#define SM_QSH   0
#define SM_KSH   9216
#define SM_VSM   27648
#define SM_PSM   46080
#define SM_DEN   55296
#define ATTN_SMEM 55552

__global__ __launch_bounds__(128, 4) void attn_kernel() {
  extern __shared__ char sm[];
  __half*   qsh = (__half*)(sm + SM_QSH);
  __half*   psm = (__half*)(sm + SM_PSM);
  float*    den = (float*)(sm + SM_DEN);

  const int tid = threadIdx.x, wid = tid >> 5, lid = tid & 31;
  const int bh = blockIdx.z*NHH + blockIdx.y;
  const int t0 = blockIdx.x * 64;
  const int tt = (tid & 15) * 4, g8 = (tid >> 4) * 8, sp0 = g8 >> 1;

  if (tid < 64) den[tid] = 0.f;

  const __half* qhg = g_qh + (size_t)bh*TT*DD;
  const __half* khg = g_kh + (size_t)bh*TT*DD;
  const __half* vhg = g_vh + (size_t)bh*TT*DD;

  // q -> qsh[d][t] (plain half, stride 72)
  for (int i = tid; i < 1024; i += 128) {
    int t = i >> 4, k4 = (i & 15) << 2;
    int tr = t0 + t; if (tr >= TT) tr = TT - 1;
    uint2 qa = *(const uint2*)(qhg + (size_t)tr*DD + k4);
    unsigned short* qs = (unsigned short*)qsh;
    qs[(k4)*72+t]   = (unsigned short)(qa.x & 0xFFFF);
    qs[(k4+1)*72+t] = (unsigned short)(qa.x >> 16);
    qs[(k4+2)*72+t] = (unsigned short)(qa.y & 0xFFFF);
    qs[(k4+3)*72+t] = (unsigned short)(qa.y >> 16);
  }

  // k prefetch (regs) / store (smem pairs)
  uint2 ka[4], kc[4];
  auto kpref = [&](int s0) {
    #pragma unroll
    for (int i = 0; i < 4; i++) {
      int j = tid + i*128;
      int sp = j >> 4, c4 = (j & 15) << 2;
      int r0 = s0 + 2*sp, r1 = r0 + 1;
      if (r0 >= TT) r0 = TT - 1;
      if (r1 >= TT) r1 = TT - 1;
      ka[i] = *(const uint2*)(khg + (size_t)r0*DD + c4);
      kc[i] = *(const uint2*)(khg + (size_t)r1*DD + c4);
    }
  };
  auto kstore = [&](unsigned* kbuf) {
    #pragma unroll
    for (int i = 0; i < 4; i++) {
      int j = tid + i*128;
      int sp = j >> 4, c4 = (j & 15) << 2;
      kbuf[(c4)*36+sp]   = __byte_perm(ka[i].x, kc[i].x, 0x5410);
      kbuf[(c4+1)*36+sp] = __byte_perm(ka[i].x, kc[i].x, 0x7632);
      kbuf[(c4+2)*36+sp] = __byte_perm(ka[i].y, kc[i].y, 0x5410);
      kbuf[(c4+3)*36+sp] = __byte_perm(ka[i].y, kc[i].y, 0x7632);
    }
  };
  auto vasync = [&](__half* vbuf, int s0) {
    #pragma unroll
    for (int i = 0; i < 4; i++) {
      int j = tid + i*128;
      int s = j >> 3, c = j & 7;
      int sr = s0 + s; if (sr >= TT) sr = TT - 1;
      unsigned dst = smem_u32(vbuf + s*72 + c*8);
      asm volatile("cp.async.ca.shared.global [%0], [%1], 16;"
                   :: "r"(dst), "l"(vhg + (size_t)sr*DD + c*8));
    }
    asm volatile("cp.async.commit_group;" ::: "memory");
  };

  // preamble: tile 0 k+v, tile 1 k regs
  kpref(0);
  kstore((unsigned*)(sm + SM_KSH));
  vasync((__half*)(sm + SM_VSM), 0);
  kpref(64);
  asm volatile("cp.async.wait_group 0;" ::: "memory");
  __syncthreads();

  const int m0 = wid * 16;
  const unsigned psm_s = smem_u32(psm);
  const unsigned aoff = ((lid & 7) + ((lid >> 4) & 1)*8)*72 + m0 + ((lid >> 3) & 1)*8;
  const unsigned boffh = ((lid & 7) + ((lid >> 3) & 1)*8)*72 + ((lid >> 4) & 1)*8;

  float oc[8][4];
  #pragma unroll
  for (int nt = 0; nt < 8; nt++)
    #pragma unroll
    for (int r = 0; r < 4; r++) oc[nt][r] = 0.f;

  for (int it = 0; it < 16; it++) {
    const int s0 = it * 64;
    const int cur = it & 1, nxt = cur ^ 1;
    unsigned* kshc = (unsigned*)(sm + SM_KSH + cur*9216);
    __half*   vsmc = (__half*)(sm + SM_VSM + cur*9216);

    if (it < 15) vasync((__half*)(sm + SM_VSM + nxt*9216), s0 + 64);

    // scores: 32-d chunks, fp32 drain
    float sacc[4][8];
    #pragma unroll
    for (int i = 0; i < 4; i++)
      #pragma unroll
      for (int j = 0; j < 8; j++) sacc[i][j] = 0.f;
    #pragma unroll
    for (int dc = 0; dc < 2; dc++) {
      __half2 sc2[4][4];
      #pragma unroll
      for (int i = 0; i < 4; i++)
        #pragma unroll
        for (int jp = 0; jp < 4; jp++) sc2[i][jp] = __float2half2_rn(0.f);
      #pragma unroll 4
      for (int dd = 0; dd < 32; dd++) {
        int d = dc*32 + dd;
        uint2 qraw = *(const uint2*)(qsh + d*72 + tt);
        unsigned qd[4];
        qd[0] = __byte_perm(qraw.x, 0, 0x1010);
        qd[1] = __byte_perm(qraw.x, 0, 0x3232);
        qd[2] = __byte_perm(qraw.y, 0, 0x1010);
        qd[3] = __byte_perm(qraw.y, 0, 0x3232);
        __half2 kk[4]; *(uint4*)kk = *(const uint4*)(kshc + d*36 + sp0);
        #pragma unroll
        for (int i = 0; i < 4; i++) {
          __half2 qq = *(__half2*)&qd[i];
          #pragma unroll
          for (int jp = 0; jp < 4; jp++)
            sc2[i][jp] = __hadd2(sc2[i][jp], habs2_(__hsub2(qq, kk[jp])));
        }
      }
      #pragma unroll
      for (int i = 0; i < 4; i++)
        #pragma unroll
        for (int jp = 0; jp < 4; jp++) {
          float2 f = __half22float2(sc2[i][jp]);
          sacc[i][2*jp]   += f.x;
          sacc[i][2*jp+1] += f.y;
        }
    }
    #pragma unroll
    for (int i = 0; i < 4; i++)
      #pragma unroll
      for (int j = 0; j < 8; j++) {
        float e;
        asm("ex2.approx.f32 %0, %1;" : "=f"(e) : "f"(sacc[i][j] * SCALE_LOG2E));
        if (s0 + g8 + j >= TT) e = 0.f;
        sacc[i][j] = e;
      }
    #pragma unroll
    for (int i = 0; i < 4; i++) {
      float ds = ((sacc[i][0]+sacc[i][1]) + (sacc[i][2]+sacc[i][3]))
               + ((sacc[i][4]+sacc[i][5]) + (sacc[i][6]+sacc[i][7]));
      atomicAdd(&den[tt + i], ds);
    }
    #pragma unroll
    for (int j = 0; j < 8; j++) {
      __half2 p01 = __floats2half2_rn(sacc[0][j], sacc[1][j]);
      __half2 p23 = __floats2half2_rn(sacc[2][j], sacc[3][j]);
      uint2 o; o.x = *(unsigned*)&p01; o.y = *(unsigned*)&p23;
      *(uint2*)(psm + (g8+j)*72 + tt) = o;
    }
    if (it < 15) {
      kstore((unsigned*)(sm + SM_KSH + nxt*9216));
      kpref(s0 + 128 < TT ? s0 + 128 : 960);
    }
    __syncthreads();

    // AV mma
    unsigned a[4][4];
    #pragma unroll
    for (int kk = 0; kk < 4; kk++) {
      unsigned ad = psm_s + (aoff + kk*16*72)*2;
      asm volatile("ldmatrix.sync.aligned.m8n8.x4.trans.shared.b16 {%0,%1,%2,%3}, [%4];"
        : "=r"(a[kk][0]),"=r"(a[kk][1]),"=r"(a[kk][2]),"=r"(a[kk][3]) : "r"(ad));
    }
    const unsigned vsm_s = smem_u32(vsmc);
    #pragma unroll
    for (int np = 0; np < 4; np++) {
      #pragma unroll
      for (int kk = 0; kk < 4; kk++) {
        unsigned b0,b1,b2,b3;
        unsigned bd = vsm_s + (boffh + kk*16*72 + np*16)*2;
        asm volatile("ldmatrix.sync.aligned.m8n8.x4.trans.shared.b16 {%0,%1,%2,%3}, [%4];"
          : "=r"(b0),"=r"(b1),"=r"(b2),"=r"(b3) : "r"(bd));
        asm volatile(
          "mma.sync.aligned.m16n8k16.row.col.f32.f16.f16.f32 "
          "{%0,%1,%2,%3}, {%4,%5,%6,%7}, {%8,%9}, {%0,%1,%2,%3};"
          : "+f"(oc[2*np][0]),"+f"(oc[2*np][1]),"+f"(oc[2*np][2]),"+f"(oc[2*np][3])
          : "r"(a[kk][0]),"r"(a[kk][1]),"r"(a[kk][2]),"r"(a[kk][3]), "r"(b0),"r"(b1));
        asm volatile(
          "mma.sync.aligned.m16n8k16.row.col.f32.f16.f16.f32 "
          "{%0,%1,%2,%3}, {%4,%5,%6,%7}, {%8,%9}, {%0,%1,%2,%3};"
          : "+f"(oc[2*np+1][0]),"+f"(oc[2*np+1][1]),"+f"(oc[2*np+1][2]),"+f"(oc[2*np+1][3])
          : "r"(a[kk][0]),"r"(a[kk][1]),"r"(a[kk][2]),"r"(a[kk][3]), "r"(b2),"r"(b3));
      }
    }
    if (it < 15) asm volatile("cp.async.wait_group 0;" ::: "memory");
    __syncthreads();
  }

  // epilogue (fp16 g_hoh)
  const int rlo = m0 + (lid >> 2), rhi = rlo + 8;
  const int tlo = t0 + rlo, thi = t0 + rhi;
  const float invlo = 1.f / (1.f + den[rlo]);
  const float invhi = 1.f / (1.f + den[rhi]);
  __half* hop = g_hoh + (size_t)bh*TT*DD;
  #pragma unroll
  for (int nt = 0; nt < 8; nt++) {
    int c = nt*8 + 2*(lid & 3);
    if (tlo < TT) {
      __half2 o = __floats2half2_rn(oc[nt][0]*invlo, oc[nt][1]*invlo);
      *(unsigned*)(hop + (size_t)tlo*DD + c) = *(unsigned*)&o;
    }
    if (thi < TT) {
      __half2 o = __floats2half2_rn(oc[nt][2]*invhi, oc[nt][3]*invhi);
      *(unsigned*)(hop + (size_t)thi*DD + c) = *(unsigned*)&o;
    }
  }
}

// K3: head-sum (fp16 in) + ReLU + Wf + residual
__global__ __launch_bounds__(256) void out_kernel(
    const float* __restrict__ x, const float* __restrict__ wf,
    float* __restrict__ out) {
  __shared__ float r[4][64];
  __shared__ float wfs[64*65];
  const int tl = threadIdx.x >> 6, w = threadIdx.x & 63;
  const int token = blockIdx.x*4 + tl, b = token / TT, t = token - b*TT;
  for (int i = threadIdx.x; i < 4160; i += 256) wfs[i] = wf[i];
  float s = 0.f;
  #pragma unroll
  for (int h = 0; h < NHH; h++)
    s += __half2float(g_hoh[((size_t)(b*NHH + h)*TT + t)*DD + w]);
  r[tl][w] = fmaxf(s, 0.f);
  __syncthreads();
  float acc = wfs[w*65 + 64];
  #pragma unroll 8
  for (int k = 0; k < 64; k++) acc += wfs[w*65 + k] * r[tl][k];
  out[(size_t)token*DD + w] = x[(size_t)token*DD + w] + acc;
}

extern "C" void kernel_launch(void* const* d_in, const int* in_sizes, int n_in,
                              void* d_out, int out_size) {
  const float* x  = (const float*)d_in[0];
  const float* wq = (const float*)d_in[1];
  const float* wv = (const float*)d_in[2];
  const float* wk = (const float*)d_in[3];
  const float* wf = (const float*)d_in[4];
  float* out = (float*)d_out;
  (void)in_sizes; (void)n_in; (void)out_size;

  cudaFuncSetAttribute(attn_kernel, cudaFuncAttributeMaxDynamicSharedMemorySize,
                       ATTN_SMEM);
  kpack_kernel<<<BB*TT/32, 256>>>(x, wk);
  qv_kernel<<<dim3(8000/64, 512/64, 2), 256>>>(x, wq, wv);
  attn_kernel<<<dim3(16, NHH, BB), 128, ATTN_SMEM>>>();
  out_kernel<<<8000/4, 256>>>(x, wf, out);
}

// round 10
// speedup vs baseline: 6.0916x; 1.0961x over previous
#include <cuda_runtime.h>
#include <cuda_fp16.h>
#include <cstdint>

#define BB  8
#define TT  1000
#define NHH 8
#define DD  64
#define SCALE_LOG2E (-0.18033688011112042f)

__device__ __half g_qh[BB*NHH*TT*DD];
__device__ __half g_kh[BB*NHH*TT*DD];
__device__ __half g_vh[BB*NHH*TT*DD];
__device__ __half g_hoh[BB*NHH*TT*DD];

__device__ __forceinline__ __half2 habs2_(__half2 a) {
  unsigned u = (*(unsigned*)&a) & 0x7FFF7FFFu;
  return *(__half2*)&u;
}
__device__ __forceinline__ unsigned smem_u32(const void* p) {
  return (unsigned)__cvta_generic_to_shared(p);
}

// K0: k = x*wk -> fp16
__global__ __launch_bounds__(256) void kpack_kernel(
    const float* __restrict__ x, const float* __restrict__ wk) {
  __shared__ float xs[32][68];
  __shared__ float wks[512];
  const int tid = threadIdx.x, tok0 = blockIdx.x * 32;
  for (int i = tid; i < 512; i += 256) wks[i] = wk[i];
  for (int i = tid; i < 512; i += 256) {
    int tl = i >> 4, k4 = (i & 15) << 2;
    float4 v = *(const float4*)&x[(tok0 + tl)*DD + k4];
    xs[tl][k4] = v.x; xs[tl][k4+1] = v.y; xs[tl][k4+2] = v.z; xs[tl][k4+3] = v.w;
  }
  __syncthreads();
  const int h = tid >> 5, tl = tid & 31;
  const int gt = tok0 + tl, b = gt / TT, t = gt - b*TT;
  __half* dst = g_kh + ((size_t)(b*NHH + h)*TT + t)*DD;
  #pragma unroll
  for (int c = 0; c < 8; c++) {
    int d = c*8;
    __half2 h0 = __floats2half2_rn(xs[tl][d]*wks[h*64+d],     xs[tl][d+1]*wks[h*64+d+1]);
    __half2 h1 = __floats2half2_rn(xs[tl][d+2]*wks[h*64+d+2], xs[tl][d+3]*wks[h*64+d+3]);
    __half2 h2 = __floats2half2_rn(xs[tl][d+4]*wks[h*64+d+4], xs[tl][d+5]*wks[h*64+d+5]);
    __half2 h3 = __floats2half2_rn(xs[tl][d+6]*wks[h*64+d+6], xs[tl][d+7]*wks[h*64+d+7]);
    uint4 o; o.x=*(unsigned*)&h0; o.y=*(unsigned*)&h1; o.z=*(unsigned*)&h2; o.w=*(unsigned*)&h3;
    *(uint4*)(dst + d) = o;
  }
}

// K1: Q/V projection -> fp16 [b,h][t][d]
__global__ __launch_bounds__(256) void qv_kernel(
    const float* __restrict__ x, const float* __restrict__ wq,
    const float* __restrict__ wv) {
  const float* w = blockIdx.z ? wv : wq;
  __half* dstg   = blockIdx.z ? g_vh : g_qh;
  const int m0 = blockIdx.x * 64, n0 = blockIdx.y * 64;
  __shared__ float xs[64*68];
  __shared__ float ws[64*68];
  const int tid = threadIdx.x;
  for (int i = tid; i < 1024; i += 256) {
    int m = i >> 4, k4 = (i & 15) << 2;
    float4 v4 = *(const float4*)&x[(m0 + m)*DD + k4];
    xs[(k4)*68+m]=v4.x; xs[(k4+1)*68+m]=v4.y; xs[(k4+2)*68+m]=v4.z; xs[(k4+3)*68+m]=v4.w;
  }
  for (int i = tid; i < 4096; i += 256) {
    int n = i >> 6, k = i & 63;
    ws[k*68 + n] = w[(n0 + n)*65 + k];
  }
  __syncthreads();
  const int tm = (tid >> 4) * 4, tn = (tid & 15) * 4;
  float acc[4][4];
  #pragma unroll
  for (int i = 0; i < 4; i++)
    #pragma unroll
    for (int j = 0; j < 4; j++) acc[i][j] = 0.f;
  #pragma unroll 8
  for (int k = 0; k < 64; k++) {
    float4 a4 = *(const float4*)&xs[k*68 + tm];
    float4 b4 = *(const float4*)&ws[k*68 + tn];
    float av[4] = {a4.x,a4.y,a4.z,a4.w}, bv[4] = {b4.x,b4.y,b4.z,b4.w};
    #pragma unroll
    for (int i = 0; i < 4; i++)
      #pragma unroll
      for (int j = 0; j < 4; j++) acc[i][j] += av[i]*bv[j];
  }
  const int n = n0 + tn, h = n >> 6, d0 = n & 63;
  float b0=w[n*65+64], b1=w[(n+1)*65+64], b2=w[(n+2)*65+64], b3=w[(n+3)*65+64];
  #pragma unroll
  for (int i = 0; i < 4; i++) {
    int m = m0 + tm + i, b = m / TT, t = m - b*TT;
    __half2 h01 = __floats2half2_rn(acc[i][0]+b0, acc[i][1]+b1);
    __half2 h23 = __floats2half2_rn(acc[i][2]+b2, acc[i][3]+b3);
    uint2 o; o.x=*(unsigned*)&h01; o.y=*(unsigned*)&h23;
    *(uint2*)(dstg + ((size_t)(b*NHH+h)*TT + t)*DD + d0) = o;
  }
}

// K2 smem: qsh2 half2[64][36] @0 (9216); ksh dup half2[64][68] @9216 (17408);
// vsm half[64][80] x2 @26624 (20480); psm half[64][72] @47104 (9216). tot 56320.
#define SM_QSH2  0
#define SM_KSH   9216
#define SM_VSM   26624
#define SM_PSM   47104
#define ATTN_SMEM 56320

__global__ __launch_bounds__(128, 4) void attn_kernel() {
  extern __shared__ char sm[];
  __half2*  qsh2 = (__half2*)(sm + SM_QSH2);
  unsigned* ksh  = (unsigned*)(sm + SM_KSH);   // dup'd half2 [d][68]
  __half*   psm  = (__half*)(sm + SM_PSM);

  const int tid = threadIdx.x, wid = tid >> 5, lid = tid & 31;
  const int bh = blockIdx.z*NHH + blockIdx.y;
  const int t0 = blockIdx.x * 64;
  const int tt = (tid & 15) * 4;       // 4 query rows (2 qpairs)
  const int qp0 = (tid & 15) * 2;      // qpair index base
  const int g8 = (tid >> 4) * 8;       // 8 sources

  const __half* qhg = g_qh + (size_t)bh*TT*DD;
  const __half* khg = g_kh + (size_t)bh*TT*DD;
  const __half* vhg = g_vh + (size_t)bh*TT*DD;

  // q -> qsh2[d][qp] = (q_{2qp}, q_{2qp+1}) packed half2
  for (int i = tid; i < 512; i += 128) {
    int qp = i >> 4, c4 = (i & 15) << 2;
    int r0 = t0 + 2*qp, r1 = r0 + 1;
    if (r0 >= TT) r0 = TT - 1;
    if (r1 >= TT) r1 = TT - 1;
    uint2 a = *(const uint2*)(qhg + (size_t)r0*DD + c4);
    uint2 c = *(const uint2*)(qhg + (size_t)r1*DD + c4);
    ((unsigned*)qsh2)[(c4)*36+qp]   = __byte_perm(a.x, c.x, 0x5410);
    ((unsigned*)qsh2)[(c4+1)*36+qp] = __byte_perm(a.x, c.x, 0x7632);
    ((unsigned*)qsh2)[(c4+2)*36+qp] = __byte_perm(a.y, c.y, 0x5410);
    ((unsigned*)qsh2)[(c4+3)*36+qp] = __byte_perm(a.y, c.y, 0x7632);
  }

  // k prefetch regs / duplicated store
  uint2 ka[4];
  auto kpref = [&](int s0) {
    #pragma unroll
    for (int i = 0; i < 4; i++) {
      int j = tid + i*128;
      int s = j >> 4, c4 = (j & 15) << 2;
      int sr = s0 + s; if (sr >= TT) sr = TT - 1;
      ka[i] = *(const uint2*)(khg + (size_t)sr*DD + c4);
    }
  };
  auto kstore = [&]() {
    #pragma unroll
    for (int i = 0; i < 4; i++) {
      int j = tid + i*128;
      int s = j >> 4, c4 = (j & 15) << 2;
      ksh[(c4)*68+s]   = __byte_perm(ka[i].x, ka[i].x, 0x1010);
      ksh[(c4+1)*68+s] = __byte_perm(ka[i].x, ka[i].x, 0x3232);
      ksh[(c4+2)*68+s] = __byte_perm(ka[i].y, ka[i].y, 0x1010);
      ksh[(c4+3)*68+s] = __byte_perm(ka[i].y, ka[i].y, 0x3232);
    }
  };
  auto vasync = [&](__half* vbuf, int s0) {
    #pragma unroll
    for (int i = 0; i < 4; i++) {
      int j = tid + i*128;
      int s = j >> 3, c = j & 7;
      int sr = s0 + s;
      bool ok = sr < TT;
      if (!ok) sr = TT - 1;
      unsigned dst = smem_u32(vbuf + s*80 + c*8);
      asm volatile("cp.async.ca.shared.global [%0], [%1], 16;"
                   :: "r"(dst), "l"(vhg + (size_t)sr*DD + c*8));
      if (c == 0) {  // ones column (col 64) for denominator; 0 if masked
        uint4 one = make_uint4(ok ? 0x00003C00u : 0u, 0u, 0u, 0u);
        *(uint4*)(vbuf + s*80 + 64) = one;
      }
    }
    asm volatile("cp.async.commit_group;" ::: "memory");
  };

  kpref(0); kstore(); kpref(64);
  vasync((__half*)(sm + SM_VSM), 0);

  const int m0 = wid * 16;
  const unsigned psm_s = smem_u32(psm);
  const unsigned aoff  = ((lid & 7) + ((lid >> 4) & 1)*8)*72 + m0 + ((lid >> 3) & 1)*8;
  const unsigned boffh = ((lid & 7) + ((lid >> 3) & 1)*8)*80 + ((lid >> 4) & 1)*8;
  const __half2 hscale = __float2half2_rn(SCALE_LOG2E);

  float oc[8][4], oce[4];
  #pragma unroll
  for (int nt = 0; nt < 8; nt++)
    #pragma unroll
    for (int r = 0; r < 4; r++) oc[nt][r] = 0.f;
  #pragma unroll
  for (int r = 0; r < 4; r++) oce[r] = 0.f;

  for (int it = 0; it < 16; it++) {
    const int s0 = it * 64;
    const int cur = it & 1;
    __half* vsmc = (__half*)(sm + SM_VSM + cur*10240);

    asm volatile("cp.async.wait_group 0;" ::: "memory");
    __syncthreads();   // ksh(it), vsm(cur), psm free

    // scores: 2 qpairs x 8 sources, full-fp16 accumulation over 64 d
    __half2 sc2[2][8];
    #pragma unroll
    for (int p = 0; p < 2; p++)
      #pragma unroll
      for (int j = 0; j < 8; j++) sc2[p][j] = __float2half2_rn(0.f);

    #pragma unroll 4
    for (int d = 0; d < 64; d++) {
      __half2 qq[2];
      *(uint2*)qq = *(const uint2*)((const unsigned*)qsh2 + d*36 + qp0);
      __half2 kk[8];
      *(uint4*)kk     = *(const uint4*)(ksh + d*68 + g8);
      *(uint4*)(kk+4) = *(const uint4*)(ksh + d*68 + g8 + 4);
      #pragma unroll
      for (int p = 0; p < 2; p++)
        #pragma unroll
        for (int j = 0; j < 8; j++)
          sc2[p][j] = __hadd2(sc2[p][j], habs2_(__hsub2(qq[p], kk[j])));
    }

    // p = exp2(scale*sum) in f16x2; mask only on last tile
    #pragma unroll
    for (int p = 0; p < 2; p++)
      #pragma unroll
      for (int j = 0; j < 8; j++) {
        __half2 e = __hmul2(sc2[p][j], hscale);
        unsigned ein = *(unsigned*)&e, eout;
        asm("ex2.approx.f16x2 %0, %1;" : "=r"(eout) : "r"(ein));
        if (it == 15 && (s0 + g8 + j >= TT)) eout = 0u;
        sc2[p][j] = *(__half2*)&eout;
      }

    // store P[s][t]
    #pragma unroll
    for (int j = 0; j < 8; j++) {
      uint2 o;
      o.x = *(unsigned*)&sc2[0][j];
      o.y = *(unsigned*)&sc2[1][j];
      *(uint2*)(psm + (g8+j)*72 + tt) = o;
    }
    __syncthreads();   // psm ready; ksh/vsm(cur) reads (scores) done

    // AV mma (+ ones column -> denominator in oce)
    unsigned a[4][4];
    #pragma unroll
    for (int kk = 0; kk < 4; kk++) {
      unsigned ad = psm_s + (aoff + kk*16*72)*2;
      asm volatile("ldmatrix.sync.aligned.m8n8.x4.trans.shared.b16 {%0,%1,%2,%3}, [%4];"
        : "=r"(a[kk][0]),"=r"(a[kk][1]),"=r"(a[kk][2]),"=r"(a[kk][3]) : "r"(ad));
    }
    const unsigned vsm_s = smem_u32(vsmc);
    #pragma unroll
    for (int np = 0; np < 4; np++) {
      #pragma unroll
      for (int kk = 0; kk < 4; kk++) {
        unsigned b0,b1,b2,b3;
        unsigned bd = vsm_s + (boffh + kk*16*80 + np*16)*2;
        asm volatile("ldmatrix.sync.aligned.m8n8.x4.trans.shared.b16 {%0,%1,%2,%3}, [%4];"
          : "=r"(b0),"=r"(b1),"=r"(b2),"=r"(b3) : "r"(bd));
        asm volatile(
          "mma.sync.aligned.m16n8k16.row.col.f32.f16.f16.f32 "
          "{%0,%1,%2,%3}, {%4,%5,%6,%7}, {%8,%9}, {%0,%1,%2,%3};"
          : "+f"(oc[2*np][0]),"+f"(oc[2*np][1]),"+f"(oc[2*np][2]),"+f"(oc[2*np][3])
          : "r"(a[kk][0]),"r"(a[kk][1]),"r"(a[kk][2]),"r"(a[kk][3]), "r"(b0),"r"(b1));
        asm volatile(
          "mma.sync.aligned.m16n8k16.row.col.f32.f16.f16.f32 "
          "{%0,%1,%2,%3}, {%4,%5,%6,%7}, {%8,%9}, {%0,%1,%2,%3};"
          : "+f"(oc[2*np+1][0]),"+f"(oc[2*np+1][1]),"+f"(oc[2*np+1][2]),"+f"(oc[2*np+1][3])
          : "r"(a[kk][0]),"r"(a[kk][1]),"r"(a[kk][2]),"r"(a[kk][3]), "r"(b2),"r"(b3));
      }
    }
    #pragma unroll
    for (int kk = 0; kk < 4; kk++) {   // ones column n-tile (cols 64..71)
      unsigned b0,b1,b2,b3;
      unsigned bd = vsm_s + (boffh + kk*16*80 + 64)*2;
      asm volatile("ldmatrix.sync.aligned.m8n8.x4.trans.shared.b16 {%0,%1,%2,%3}, [%4];"
        : "=r"(b0),"=r"(b1),"=r"(b2),"=r"(b3) : "r"(bd));
      asm volatile(
        "mma.sync.aligned.m16n8k16.row.col.f32.f16.f16.f32 "
        "{%0,%1,%2,%3}, {%4,%5,%6,%7}, {%8,%9}, {%0,%1,%2,%3};"
        : "+f"(oce[0]),"+f"(oce[1]),"+f"(oce[2]),"+f"(oce[3])
        : "r"(a[kk][0]),"r"(a[kk][1]),"r"(a[kk][2]),"r"(a[kk][3]), "r"(b0),"r"(b1));
      (void)b2; (void)b3;
    }

    if (it < 15) {
      kstore();
      kpref(s0 + 128 < TT ? s0 + 128 : 960);
      vasync((__half*)(sm + SM_VSM + (cur^1)*10240), s0 + 64);
    }
  }

  // epilogue: den from ones column (lanes lid&3==0 hold col 64)
  float den_lo = __shfl_sync(0xFFFFFFFFu, oce[0], lid & 28);
  float den_hi = __shfl_sync(0xFFFFFFFFu, oce[2], lid & 28);
  const int rlo = m0 + (lid >> 2), rhi = rlo + 8;
  const int tlo = t0 + rlo, thi = t0 + rhi;
  const float invlo = 1.f / (1.f + den_lo);
  const float invhi = 1.f / (1.f + den_hi);
  __half* hop = g_hoh + (size_t)bh*TT*DD;
  #pragma unroll
  for (int nt = 0; nt < 8; nt++) {
    int c = nt*8 + 2*(lid & 3);
    if (tlo < TT) {
      __half2 o = __floats2half2_rn(oc[nt][0]*invlo, oc[nt][1]*invlo);
      *(unsigned*)(hop + (size_t)tlo*DD + c) = *(unsigned*)&o;
    }
    if (thi < TT) {
      __half2 o = __floats2half2_rn(oc[nt][2]*invhi, oc[nt][3]*invhi);
      *(unsigned*)(hop + (size_t)thi*DD + c) = *(unsigned*)&o;
    }
  }
}

// K3: head-sum (fp16 in) + ReLU + Wf + residual
__global__ __launch_bounds__(256) void out_kernel(
    const float* __restrict__ x, const float* __restrict__ wf,
    float* __restrict__ out) {
  __shared__ float r[4][64];
  __shared__ float wfs[64*65];
  const int tl = threadIdx.x >> 6, w = threadIdx.x & 63;
  const int token = blockIdx.x*4 + tl, b = token / TT, t = token - b*TT;
  for (int i = threadIdx.x; i < 4160; i += 256) wfs[i] = wf[i];
  float s = 0.f;
  #pragma unroll
  for (int h = 0; h < NHH; h++)
    s += __half2float(g_hoh[((size_t)(b*NHH + h)*TT + t)*DD + w]);
  r[tl][w] = fmaxf(s, 0.f);
  __syncthreads();
  float acc = wfs[w*65 + 64];
  #pragma unroll 8
  for (int k = 0; k < 64; k++) acc += wfs[w*65 + k] * r[tl][k];
  out[(size_t)token*DD + w] = x[(size_t)token*DD + w] + acc;
}

extern "C" void kernel_launch(void* const* d_in, const int* in_sizes, int n_in,
                              void* d_out, int out_size) {
  const float* x  = (const float*)d_in[0];
  const float* wq = (const float*)d_in[1];
  const float* wv = (const float*)d_in[2];
  const float* wk = (const float*)d_in[3];
  const float* wf = (const float*)d_in[4];
  float* out = (float*)d_out;
  (void)in_sizes; (void)n_in; (void)out_size;

  cudaFuncSetAttribute(attn_kernel, cudaFuncAttributeMaxDynamicSharedMemorySize,
                       ATTN_SMEM);
  kpack_kernel<<<BB*TT/32, 256>>>(x, wk);
  qv_kernel<<<dim3(8000/64, 512/64, 2), 256>>>(x, wq, wv);
  attn_kernel<<<dim3(16, NHH, BB), 128, ATTN_SMEM>>>();
  out_kernel<<<8000/4, 256>>>(x, wf, out);
}